// round 16
// baseline (speedup 1.0000x reference)
#include <cuda_runtime.h>
#include <math.h>

#define NLEV 16
#define TABLE_SIZE (1u << 19)
#define TMASK (TABLE_SIZE - 1u)
#define PRIME_Y 2654435761u
#define PRIME_Z 805459861u
#define TPB 256
#define STAGES 3

#define NBITS_DIM 6
#define NBINS (1 << (3 * NBITS_DIM))     // 262144
#define CAP   (1 << 20)                  // max points we can sort

struct InvArr { float v[NLEV]; };        // res/2 per level

__device__ unsigned g_hist[NBINS];
__device__ float4   g_pts[CAP];          // {x0,x1,x2, orig_idx as bits}

// ---------------- Morton key (shared by hist & scatter) ---------------------
__device__ __forceinline__ unsigned part3(unsigned v) {
    v &= 0x3FFu;
    v = (v | (v << 16)) & 0x030000FFu;
    v = (v | (v << 8))  & 0x0300F00Fu;
    v = (v | (v << 4))  & 0x030C30C3u;
    v = (v | (v << 2))  & 0x09249249u;
    return v;
}
__device__ __forceinline__ unsigned morton_key(float x0, float x1, float x2) {
    x0 = fminf(fmaxf(x0, -1.f), 1.f);
    x1 = fminf(fmaxf(x1, -1.f), 1.f);
    x2 = fminf(fmaxf(x2, -1.f), 1.f);
    unsigned q0 = min(63, (int)((x0 + 1.f) * 32.f));
    unsigned q1 = min(63, (int)((x1 + 1.f) * 32.f));
    unsigned q2 = min(63, (int)((x2 + 1.f) * 32.f));
    return part3(q0) | (part3(q1) << 1) | (part3(q2) << 2);
}

// ---------------- sort kernels ----------------------------------------------
__global__ void zero_hist() {
    int i = blockIdx.x * blockDim.x + threadIdx.x;
    if (i < NBINS) g_hist[i] = 0u;
}

__global__ void hist_kernel(const float* __restrict__ x, int n) {
    int i = blockIdx.x * blockDim.x + threadIdx.x;
    if (i >= n) return;
    unsigned k = morton_key(x[3 * i], x[3 * i + 1], x[3 * i + 2]);
    atomicAdd(&g_hist[k], 1u);
}

__global__ void scan_hist() {             // single block, 1024 threads
    __shared__ unsigned s[1024];
    const int t = threadIdx.x;
    unsigned carry = 0;
    for (int c = 0; c < NBINS / 1024; ++c) {
        const int idx = c * 1024 + t;
        const unsigned v = g_hist[idx];
        s[t] = v;
        __syncthreads();
        for (int off = 1; off < 1024; off <<= 1) {
            unsigned u = (t >= off) ? s[t - off] : 0u;
            __syncthreads();
            s[t] += u;
            __syncthreads();
        }
        const unsigned excl = s[t] - v + carry;
        const unsigned tot  = s[1023];
        __syncthreads();                   // everyone read s before next chunk
        g_hist[idx] = excl;
        carry += tot;
    }
}

__global__ void scatter_kernel(const float* __restrict__ x, int n) {
    int i = blockIdx.x * blockDim.x + threadIdx.x;
    if (i >= n) return;
    const float x0 = x[3 * i], x1 = x[3 * i + 1], x2 = x[3 * i + 2];
    const unsigned k = morton_key(x0, x1, x2);
    const unsigned pos = atomicAdd(&g_hist[k], 1u);
    g_pts[pos] = make_float4(x0, x1, x2, __uint_as_float((unsigned)i));
}

// ---------------- LDG load phase (same as R9 best) --------------------------
// PRIME_X == 1: even bl.x -> corner pair (h, h^1) = one aligned float4 load.
__device__ __forceinline__ void load_level(
    const float* __restrict__ emb, int lvl, float invg,
    float X0, float X1, float X2,
    float4 e[4], unsigned& meta4, float& w0, float& w1, float& w2)
{
    const float t0 = X0 * invg, t1 = X1 * invg, t2 = X2 * invg;
    const float f0 = floorf(t0), f1 = floorf(t1), f2 = floorf(t2);
    w0 = t0 - f0; w1 = t1 - f1; w2 = t2 - f2;

    const unsigned hx = (unsigned)(int)f0;
    const unsigned hy = (unsigned)(int)f1 * PRIME_Y;
    const unsigned hz = (unsigned)(int)f2 * PRIME_Z;
    const unsigned r0 = hy ^ hz;
    const unsigned r1 = hy ^ (hz + PRIME_Z);
    const unsigned r2 = (hy + PRIME_Y) ^ hz;
    const unsigned r3 = (hy + PRIME_Y) ^ (hz + PRIME_Z);
    const unsigned h0 = (hx ^ r0) & TMASK, h1 = (hx ^ r1) & TMASK;
    const unsigned h2 = (hx ^ r2) & TMASK, h3 = (hx ^ r3) & TMASK;

    const float2* tab2 = (const float2*)emb + (size_t)lvl * TABLE_SIZE;
    const float4* tab4 = (const float4*)tab2;

    if ((hx & 1u) == 0u) {
        e[0] = __ldg(&tab4[h0 >> 1]);
        e[1] = __ldg(&tab4[h1 >> 1]);
        e[2] = __ldg(&tab4[h2 >> 1]);
        e[3] = __ldg(&tab4[h3 >> 1]);
        meta4 = (h0 & 1u) | ((h1 & 1u) << 1) | ((h2 & 1u) << 2) | ((h3 & 1u) << 3);
    } else {
        const unsigned hx1 = hx + 1u;
        const unsigned g0 = (hx1 ^ r0) & TMASK, g1 = (hx1 ^ r1) & TMASK;
        const unsigned g2 = (hx1 ^ r2) & TMASK, g3 = (hx1 ^ r3) & TMASK;
        float2 a0 = __ldg(&tab2[h0]), b0 = __ldg(&tab2[g0]);
        float2 a1 = __ldg(&tab2[h1]), b1 = __ldg(&tab2[g1]);
        float2 a2 = __ldg(&tab2[h2]), b2 = __ldg(&tab2[g2]);
        float2 a3 = __ldg(&tab2[h3]), b3 = __ldg(&tab2[g3]);
        e[0] = make_float4(a0.x, a0.y, b0.x, b0.y);
        e[1] = make_float4(a1.x, a1.y, b1.x, b1.y);
        e[2] = make_float4(a2.x, a2.y, b2.x, b2.y);
        e[3] = make_float4(a3.x, a3.y, b3.x, b3.y);
        meta4 = 0u;
    }
}

__device__ __forceinline__ void consume_level(
    const float4 e[4], unsigned meta4,
    float w0, float w1, float w2, float& a0, float& a1)
{
    const float u0 = 1.f - w0, u1 = 1.f - w1, u2 = 1.f - w2;
    float c[4];
    c[0] = u1 * u2; c[1] = u1 * w2; c[2] = w1 * u2; c[3] = w1 * w2;
    a0 = 0.f; a1 = 0.f;
#pragma unroll
    for (int k = 0; k < 4; ++k) {
        const bool sw = (meta4 >> k) & 1u;
        const float wA = c[k] * (sw ? w0 : u0);   // weight for slots .xy
        const float wB = c[k] * (sw ? u0 : w0);   // weight for slots .zw
        a0 = fmaf(wA, e[k].x, fmaf(wB, e[k].z, a0));
        a1 = fmaf(wA, e[k].y, fmaf(wB, e[k].w, a1));
    }
}

// ---------------- main kernel -----------------------------------------------
__global__ void __launch_bounds__(TPB, 3)
ingp_hash_kernel(const float* __restrict__ x,
                 const float* __restrict__ emb,
                 float* __restrict__ out,
                 int n, int sorted, InvArr inv)
{
    // per-thread scratch rows, pitch 33 -> conflict-free writes and reads
    __shared__ float stage[TPB * 33];

    const int tid = threadIdx.x;
    const int pid = blockIdx.x * TPB + tid;
    if (pid >= n) return;                  // no barriers below, safe to exit

    float x0, x1, x2;
    unsigned j;
    if (sorted) {
        const float4 p = g_pts[pid];       // coalesced: {x,y,z,orig idx}
        x0 = p.x; x1 = p.y; x2 = p.z; j = __float_as_uint(p.w);
    } else {
        j = (unsigned)pid;
        x0 = x[3 * pid + 0];
        x1 = x[3 * pid + 1];
        x2 = x[3 * pid + 2];
    }
    x0 = fminf(fmaxf(x0, -1.f), 1.f);
    x1 = fminf(fmaxf(x1, -1.f), 1.f);
    x2 = fminf(fmaxf(x2, -1.f), 1.f);
    const float X0 = x0 + 1.f, X1 = x1 + 1.f, X2 = x2 + 1.f;

    // 3-stage software pipeline over levels (R9 structure)
    float4 eb[STAGES][4];
    float w0b[STAGES], w1b[STAGES], w2b[STAGES];
    unsigned mArr[STAGES];

    load_level(emb, 0, inv.v[0], X0, X1, X2, eb[0], mArr[0], w0b[0], w1b[0], w2b[0]);
    load_level(emb, 1, inv.v[1], X0, X1, X2, eb[1], mArr[1], w0b[1], w1b[1], w2b[1]);

#pragma unroll
    for (int lvl = 0; lvl < NLEV; ++lvl) {
        const int cur = lvl % STAGES;
        if (lvl + 2 < NLEV) {
            const int nxt = (lvl + 2) % STAGES;
            load_level(emb, lvl + 2, inv.v[lvl + 2], X0, X1, X2,
                       eb[nxt], mArr[nxt], w0b[nxt], w1b[nxt], w2b[nxt]);
        }
        float a0, a1;
        consume_level(eb[cur], mArr[cur], w0b[cur], w1b[cur], w2b[cur], a0, a1);
        stage[tid * 33 + 2 * lvl + 0] = a0;
        stage[tid * 33 + 2 * lvl + 1] = a1;
    }

    // write this point's 32 floats to its original slot (128B, 8x STG.128)
    float4* op = (float4*)(out + (size_t)j * 32);
#pragma unroll
    for (int k = 0; k < 8; ++k) {
        float4 v;
        v.x = stage[tid * 33 + 4 * k + 0];
        v.y = stage[tid * 33 + 4 * k + 1];
        v.z = stage[tid * 33 + 4 * k + 2];
        v.w = stage[tid * 33 + 4 * k + 3];
        __stcs(&op[k], v);
    }
}

extern "C" void kernel_launch(void* const* d_in, const int* in_sizes, int n_in,
                              void* d_out, int out_size)
{
    const float* x   = (const float*)d_in[0];
    const float* emb = (const float*)d_in[1];
    float* out = (float*)d_out;

    const int n = in_sizes[0] / 3;

    InvArr inv;
    {
        const double b = exp((log(512.0) - log(16.0)) / 15.0);
        for (int i = 0; i < NLEV; ++i)
            inv.v[i] = (float)(floor(16.0 * pow(b, (double)i)) * 0.5);
    }

    const int sorted = (n <= CAP) ? 1 : 0;

    if (sorted) {
        zero_hist<<<(NBINS + 255) / 256, 256>>>();
        hist_kernel<<<(n + 255) / 256, 256>>>(x, n);
        scan_hist<<<1, 1024>>>();
        scatter_kernel<<<(n + 255) / 256, 256>>>(x, n);
    }

    const int grid = (n + TPB - 1) / TPB;
    ingp_hash_kernel<<<grid, TPB>>>(x, emb, out, n, sorted, inv);
}